// round 5
// baseline (speedup 1.0000x reference)
// v4 (identical to audited R1-R3 source; resubmitted after 5th broker GPUAcquisitionTimeout)
#include <cuda_runtime.h>
#include <cuda_bf16.h>

typedef unsigned long long ull;

// ---------------- problem constants ----------------
#define NV    5
#define H0    512
#define W0    640
#define H1    256
#define W1    320
#define H2    128
#define W2    160
#define HF    64
#define WF    80
#define CF    32
#define ND    128

// ---------------- scratch (device globals; no allocations allowed) ----------------
__device__ float g_x1[NV*8*H1*W1];          // encoder stage 1 out
__device__ float g_x2[NV*16*H2*W2];         // encoder stage 2 out
__device__ float g_fe[NV*HF*WF*CF];         // features, channel-last [v][h][w][c]
__device__ float g_cost[ND*HF*WF*CF];       // cost volume, channel-last [d][h][w][c]
__device__ float g_r1[ND*HF*WF*8];          // reg conv1 out, channel-last [d][h][w][o]
__device__ float g_r2[ND*HF*WF];            // reg conv2 out [d][h][w]
__device__ float g_prob[ND*HF*WF];          // exp buffer
__device__ float g_reglow[HF*WF];
__device__ float g_conflow[HF*WF];
__device__ float g_regup[H0*W0];
__device__ float g_hid[H0*W0*32];           // refinement hidden, channel-last
__device__ float g_M[4][9];                 // per-view homography 3x3 (K R K^-1)
__device__ float g_T[4][3];                 // K t
__device__ float g_depth[ND];

// ---------------- f32x2 packed helpers (sm_10x) ----------------
__device__ __forceinline__ ull pk2(float lo, float hi) {
    ull r; asm("mov.b64 %0, {%1,%2};" : "=l"(r) : "f"(lo), "f"(hi)); return r;
}
__device__ __forceinline__ void fma2(ull &d, ull a, ull b) {
    asm("fma.rn.f32x2 %0, %1, %2, %3;" : "=l"(d) : "l"(a), "l"(b), "l"(d));
}
__device__ __forceinline__ float2 unpk2(ull v) {
    float2 r; asm("mov.b64 {%0,%1}, %2;" : "=f"(r.x), "=f"(r.y) : "l"(v)); return r;
}

// ---------------- init: camera matrices + depth hypotheses ----------------
__global__ void k_init(const float* __restrict__ K, const float* __restrict__ poses) {
    // single thread; double precision for composition accuracy
    double Kf[9];
    for (int i = 0; i < 9; i++) Kf[i] = (double)K[i];
    for (int i = 0; i < 6; i++) Kf[i] *= 0.125;  // scale first two rows by 1/SCALE

    // inverse of Kf (general 3x3)
    double a=Kf[0],b=Kf[1],c=Kf[2],d=Kf[3],e=Kf[4],f=Kf[5],g=Kf[6],h=Kf[7],ii=Kf[8];
    double det = a*(e*ii-f*h) - b*(d*ii-f*g) + c*(d*h-e*g);
    double id_ = 1.0/det;
    double inv[9] = {(e*ii-f*h)*id_, (c*h-b*ii)*id_, (b*f-c*e)*id_,
                     (f*g-d*ii)*id_, (a*ii-c*g)*id_, (c*d-a*f)*id_,
                     (d*h-e*g)*id_, (b*g-a*h)*id_, (a*e-b*d)*id_};

    // rigid inverse of poses[0]
    const float* P0 = poses;
    double R0T[9], t0[3], it0[3];
    for (int r = 0; r < 3; r++)
        for (int cc = 0; cc < 3; cc++) R0T[r*3+cc] = (double)P0[cc*4+r];
    t0[0]=P0[3]; t0[1]=P0[7]; t0[2]=P0[11];
    for (int r = 0; r < 3; r++)
        it0[r] = -(R0T[r*3+0]*t0[0] + R0T[r*3+1]*t0[1] + R0T[r*3+2]*t0[2]);

    for (int v = 1; v < NV; v++) {
        const float* P = poses + v*16;
        double Rt[9], tt[3], A[9];
        for (int r = 0; r < 3; r++) {
            for (int cc = 0; cc < 3; cc++) {
                double s = 0;
                for (int k = 0; k < 3; k++) s += (double)P[r*4+k] * R0T[k*3+cc];
                Rt[r*3+cc] = s;
            }
            double s = (double)P[r*4+3];
            for (int k = 0; k < 3; k++) s += (double)P[r*4+k] * it0[k];
            tt[r] = s;
        }
        for (int r = 0; r < 3; r++)
            for (int cc = 0; cc < 3; cc++) {
                double s = 0;
                for (int k = 0; k < 3; k++) s += Kf[r*3+k] * Rt[k*3+cc];
                A[r*3+cc] = s;
            }
        for (int r = 0; r < 3; r++) {
            for (int cc = 0; cc < 3; cc++) {
                double s = 0;
                for (int k = 0; k < 3; k++) s += A[r*3+k] * inv[k*3+cc];
                g_M[v-1][r*3+cc] = (float)s;
            }
            double s = 0;
            for (int k = 0; k < 3; k++) s += Kf[r*3+k] * tt[k];
            g_T[v-1][r] = (float)s;
        }
    }
    for (int i = 0; i < ND; i++) {
        float dinv = 2.0f + (0.2f - 2.0f) * ((float)i / 127.0f);
        g_depth[i] = 1.0f / dinv;
    }
}

// ---------------- encoder conv1: 3->8, stride 2, relu ----------------
__global__ void __launch_bounds__(256) k_enc1(const float* __restrict__ img,
                                              const float* __restrict__ W,
                                              const float* __restrict__ Bi) {
    __shared__ float ws[216];   // [(ci*9+tap)*8 + co]
    __shared__ float bs[8];
    for (int i = threadIdx.x; i < 216; i += blockDim.x) {
        int co = i & 7; int rest = i >> 3; int tap = rest % 9; int ci = rest / 9;
        ws[i] = W[(co*3+ci)*9 + tap];
    }
    if (threadIdx.x < 8) bs[threadIdx.x] = Bi[threadIdx.x];
    __syncthreads();

    int id = blockIdx.x*blockDim.x + threadIdx.x;      // exactly NV*H1*W1 threads
    int ow = id % W1; int oh = (id / W1) % H1; int n = id / (W1*H1);
    float acc[8];
    #pragma unroll
    for (int o = 0; o < 8; o++) acc[o] = bs[o];
    const float* ib = img + n*3*H0*W0;
    for (int ci = 0; ci < 3; ci++)
        #pragma unroll
        for (int kh = 0; kh < 3; kh++) {
            int ih = 2*oh + kh; if (ih >= H0) continue;
            #pragma unroll
            for (int kw = 0; kw < 3; kw++) {
                int iw = 2*ow + kw; if (iw >= W0) continue;
                float v = ib[(ci*H0+ih)*W0 + iw];
                const float* wp = ws + (ci*9 + kh*3 + kw)*8;
                #pragma unroll
                for (int o = 0; o < 8; o++) acc[o] += wp[o]*v;
            }
        }
    #pragma unroll
    for (int o = 0; o < 8; o++)
        g_x1[((n*8+o)*H1 + oh)*W1 + ow] = fmaxf(acc[o], 0.f);
}

// ---------------- encoder conv2: 8->16, stride 2, relu ----------------
__global__ void __launch_bounds__(256) k_enc2(const float* __restrict__ W,
                                              const float* __restrict__ Bi) {
    __shared__ float ws[1152];  // [(ci*9+tap)*16 + co]
    __shared__ float bs[16];
    for (int i = threadIdx.x; i < 1152; i += blockDim.x) {
        int co = i & 15; int rest = i >> 4; int tap = rest % 9; int ci = rest / 9;
        ws[i] = W[(co*8+ci)*9 + tap];
    }
    if (threadIdx.x < 16) bs[threadIdx.x] = Bi[threadIdx.x];
    __syncthreads();

    int id = blockIdx.x*blockDim.x + threadIdx.x;      // NV*H2*W2 threads
    int ow = id % W2; int oh = (id / W2) % H2; int n = id / (W2*H2);
    float acc[16];
    #pragma unroll
    for (int o = 0; o < 16; o++) acc[o] = bs[o];
    const float* ib = g_x1 + n*8*H1*W1;
    for (int ci = 0; ci < 8; ci++)
        #pragma unroll
        for (int kh = 0; kh < 3; kh++) {
            int ih = 2*oh + kh; if (ih >= H1) continue;
            #pragma unroll
            for (int kw = 0; kw < 3; kw++) {
                int iw = 2*ow + kw; if (iw >= W1) continue;
                float v = ib[(ci*H1+ih)*W1 + iw];
                const float* wp = ws + (ci*9 + kh*3 + kw)*16;
                #pragma unroll
                for (int o = 0; o < 16; o++) acc[o] += wp[o]*v;
            }
        }
    #pragma unroll
    for (int o = 0; o < 16; o++)
        g_x2[((n*16+o)*H2 + oh)*W2 + ow] = fmaxf(acc[o], 0.f);
}

// ---------------- encoder conv3: 16->32, stride 2, NO relu, channel-last out ----------------
__global__ void __launch_bounds__(256) k_enc3(const float* __restrict__ W,
                                              const float* __restrict__ Bi) {
    __shared__ float ws[4608];  // [(ci*9+tap)*32 + co]
    __shared__ float bs[32];
    for (int i = threadIdx.x; i < 4608; i += blockDim.x) {
        int co = i & 31; int rest = i >> 5; int tap = rest % 9; int ci = rest / 9;
        ws[i] = W[(co*16+ci)*9 + tap];
    }
    if (threadIdx.x < 32) bs[threadIdx.x] = Bi[threadIdx.x];
    __syncthreads();

    int id = blockIdx.x*blockDim.x + threadIdx.x;      // 4 * NV*HF*WF threads
    int cog = id & 3; int pix = id >> 2;
    int ow = pix % WF; int oh = (pix / WF) % HF; int n = pix / (WF*HF);
    float acc[8];
    #pragma unroll
    for (int o = 0; o < 8; o++) acc[o] = bs[cog*8 + o];
    const float* ib = g_x2 + n*16*H2*W2;
    for (int ci = 0; ci < 16; ci++)
        #pragma unroll
        for (int kh = 0; kh < 3; kh++) {
            int ih = 2*oh + kh; if (ih >= H2) continue;
            #pragma unroll
            for (int kw = 0; kw < 3; kw++) {
                int iw = 2*ow + kw; if (iw >= W2) continue;
                float v = ib[(ci*H2+ih)*W2 + iw];
                const float* wp = ws + (ci*9 + kh*3 + kw)*32 + cog*8;
                #pragma unroll
                for (int o = 0; o < 8; o++) acc[o] += wp[o]*v;
            }
        }
    #pragma unroll
    for (int o = 0; o < 8; o++)
        g_fe[((n*HF+oh)*WF + ow)*CF + cog*8 + o] = acc[o];
}

// ---------------- cost volume: block per (h,w), warp strides depth, lane = channel ----------------
__device__ __forceinline__ float samp_fe(const float* fb, int x, int y) {
    return (x >= 0 && x < WF && y >= 0 && y < HF) ? fb[(y*WF + x)*CF] : 0.f;
}

__global__ void __launch_bounds__(128) k_cost() {
    int pix = blockIdx.x;                  // HF*WF blocks
    int w = pix % WF, h = pix / WF;
    int lane = threadIdx.x & 31, warp = threadIdx.x >> 5;
    float fx = (float)w, fy = (float)h;
    float bx[4], by[4], bz[4], tx[4], ty[4], tz[4];
    #pragma unroll
    for (int v = 0; v < 4; v++) {
        bx[v] = g_M[v][0]*fx + g_M[v][1]*fy + g_M[v][2];
        by[v] = g_M[v][3]*fx + g_M[v][4]*fy + g_M[v][5];
        bz[v] = g_M[v][6]*fx + g_M[v][7]*fy + g_M[v][8];
        tx[v] = g_T[v][0]; ty[v] = g_T[v][1]; tz[v] = g_T[v][2];
    }
    float ref = g_fe[pix*CF + lane];
    float refsq = ref*ref;

    for (int d = warp; d < ND; d += 4) {
        float dep = g_depth[d];
        float s = ref, ss = refsq;
        #pragma unroll
        for (int v = 0; v < 4; v++) {
            float zz = dep*bz[v] + tz[v];
            float val = 0.f;
            if (zz > 0.001f) {
                float iz = 1.f / zz;
                float px = (dep*bx[v] + tx[v]) * iz;
                float py = (dep*by[v] + ty[v]) * iz;
                float xf = floorf(px), yf = floorf(py);
                float wx = px - xf, wy = py - yf;
                int x0 = (int)xf, y0 = (int)yf;
                const float* fb = g_fe + (v+1)*(HF*WF*CF) + lane;
                float v00 = samp_fe(fb, x0,   y0);
                float v01 = samp_fe(fb, x0+1, y0);
                float v10 = samp_fe(fb, x0,   y0+1);
                float v11 = samp_fe(fb, x0+1, y0+1);
                val = v00*(1.f-wx)*(1.f-wy) + v01*wx*(1.f-wy)
                    + v10*(1.f-wx)*wy       + v11*wx*wy;
            }
            s += val; ss += val*val;
        }
        float m = s * 0.2f;
        g_cost[((d*HF + h)*WF + w)*CF + lane] = ss*0.2f - m*m;
    }
}

// ---------------- 3D conv #1: 32->8, 3x3x3, relu. f32x2-packed, 2 voxels/thread ----------------
__global__ void __launch_bounds__(128) k_reg1(const float* __restrict__ W,
                                              const float* __restrict__ Bi) {
    __shared__ __align__(8) float sw[6912];   // [tap*256 + o*32 + c]  (c-pairs 8B aligned)
    for (int i = threadIdx.x; i < 6912; i += 128) {
        int tap = i >> 8; int r = i & 255; int o = r >> 5; int c = r & 31;
        sw[i] = W[(o*32+c)*27 + tap];
    }
    __syncthreads();

    int id = blockIdx.x*128 + threadIdx.x;    // ND*HF*(WF/2) threads
    int wp = id % (WF/2); int h = (id/(WF/2)) % HF; int d = id / ((WF/2)*HF);
    int w0 = wp*2;

    ull acc[16];
    #pragma unroll
    for (int i = 0; i < 16; i++) acc[i] = 0ull;

    for (int kd = 0; kd < 3; kd++) {
        int dd = d + kd - 1; if ((unsigned)dd >= ND) continue;
        #pragma unroll
        for (int kh = 0; kh < 3; kh++) {
            int hh = h + kh - 1; if ((unsigned)hh >= HF) continue;
            const float* rowp = g_cost + ((dd*HF + hh)*WF)*CF;
            #pragma unroll
            for (int kw = 0; kw < 3; kw++) {
                int wa = w0 + kw - 1;
                int wb = wa + 1;
                const float4* pa = (wa >= 0 && wa < WF) ? (const float4*)(rowp + wa*CF) : (const float4*)0;
                const float4* pb = (wb < WF)            ? (const float4*)(rowp + wb*CF) : (const float4*)0;
                const float* tw = sw + ((kd*3+kh)*3 + kw)*256;
                #pragma unroll
                for (int c4 = 0; c4 < 8; c4++) {
                    float4 A  = pa ? pa[c4] : make_float4(0.f,0.f,0.f,0.f);
                    float4 Bv = pb ? pb[c4] : make_float4(0.f,0.f,0.f,0.f);
                    ull a0 = pk2(A.x, A.y),  a1 = pk2(A.z, A.w);
                    ull b0 = pk2(Bv.x, Bv.y), b1 = pk2(Bv.z, Bv.w);
                    #pragma unroll
                    for (int o = 0; o < 8; o++) {
                        ull w01 = *(const ull*)(tw + o*32 + c4*4);
                        ull w23 = *(const ull*)(tw + o*32 + c4*4 + 2);
                        fma2(acc[o],     w01, a0);
                        fma2(acc[o],     w23, a1);
                        fma2(acc[8+o],   w01, b0);
                        fma2(acc[8+o],   w23, b1);
                    }
                }
            }
        }
    }

    int ob = ((d*HF + h)*WF + w0)*8;
    #pragma unroll
    for (int o = 0; o < 8; o++) {
        float bia = Bi[o];
        float2 fa = unpk2(acc[o]);
        float2 fb = unpk2(acc[8+o]);
        g_r1[ob + o]     = fmaxf(fa.x + fa.y + bia, 0.f);
        g_r1[ob + 8 + o] = fmaxf(fb.x + fb.y + bia, 0.f);
    }
}

// ---------------- 3D conv #2: 8->1, 3x3x3 ----------------
__global__ void __launch_bounds__(256) k_reg2(const float* __restrict__ W,
                                              const float* __restrict__ Bi) {
    __shared__ float sw[216];   // [tap*8 + o]
    for (int i = threadIdx.x; i < 216; i += blockDim.x) {
        int o = i & 7; int tap = i >> 3;
        sw[i] = W[o*27 + tap];
    }
    __syncthreads();

    int id = blockIdx.x*blockDim.x + threadIdx.x;   // ND*HF*WF threads
    int w = id % WF; int h = (id / WF) % HF; int d = id / (WF*HF);
    float acc = Bi[0];
    for (int kd = 0; kd < 3; kd++) {
        int dd = d + kd - 1; if ((unsigned)dd >= ND) continue;
        #pragma unroll
        for (int kh = 0; kh < 3; kh++) {
            int hh = h + kh - 1; if ((unsigned)hh >= HF) continue;
            #pragma unroll
            for (int kw = 0; kw < 3; kw++) {
                int ww = w + kw - 1; if ((unsigned)ww >= WF) continue;
                const float4* p = (const float4*)(g_r1 + ((dd*HF+hh)*WF + ww)*8);
                float4 A = p[0], B = p[1];
                const float* tw = sw + ((kd*3+kh)*3 + kw)*8;
                acc += A.x*tw[0] + A.y*tw[1] + A.z*tw[2] + A.w*tw[3]
                     + B.x*tw[4] + B.y*tw[5] + B.z*tw[6] + B.w*tw[7];
            }
        }
    }
    g_r2[id] = acc;
}

// ---------------- softmax over depth + regression + sliding-window confidence ----------------
__global__ void __launch_bounds__(256) k_soft() {
    int pix = blockIdx.x*blockDim.x + threadIdx.x;   // HF*WF threads
    float mx = -1e30f;
    for (int d = 0; d < ND; d++) mx = fmaxf(mx, g_r2[d*(HF*WF) + pix]);
    float sum = 0.f;
    for (int d = 0; d < ND; d++) {
        float e = expf(g_r2[d*(HF*WF) + pix] - mx);
        g_prob[d*(HF*WF) + pix] = e;
        sum += e;
    }
    float invs = 1.f / sum;
    float reg = 0.f, conf = -1e30f;
    float p1 = 0.f, p2 = 0.f, p3 = 0.f;
    for (int j = 0; j < ND + 2; j++) {
        float cur = 0.f;
        if (j < ND) {
            cur = g_prob[j*(HF*WF) + pix] * invs;
            reg += cur * g_depth[j];
        }
        float s4 = cur + p1 + p2 + p3;
        if (j >= 2) conf = fmaxf(conf, s4);
        p3 = p2; p2 = p1; p1 = cur;
    }
    g_reglow[pix]  = reg;
    g_conflow[pix] = conf;
}

// ---------------- bilinear upsample 8x (jax.image.resize: half-pixel, clamped) ----------------
__global__ void __launch_bounds__(256) k_up(float* __restrict__ out) {
    int id = blockIdx.x*blockDim.x + threadIdx.x;   // H0*W0 threads
    int ow = id % W0; int oh = id / W0;
    float sy = fminf(fmaxf((oh + 0.5f)*0.125f - 0.5f, 0.f), (float)(HF-1));
    float sx = fminf(fmaxf((ow + 0.5f)*0.125f - 0.5f, 0.f), (float)(WF-1));
    int y0 = (int)sy, x0 = (int)sx;
    float fy = sy - y0, fx = sx - x0;
    int y1 = min(y0+1, HF-1), x1 = min(x0+1, WF-1);
    float w00 = (1.f-fy)*(1.f-fx), w01 = (1.f-fy)*fx, w10 = fy*(1.f-fx), w11 = fy*fx;
    float r = g_reglow[y0*WF+x0]*w00 + g_reglow[y0*WF+x1]*w01
            + g_reglow[y1*WF+x0]*w10 + g_reglow[y1*WF+x1]*w11;
    float c = g_conflow[y0*WF+x0]*w00 + g_conflow[y0*WF+x1]*w01
            + g_conflow[y1*WF+x0]*w10 + g_conflow[y1*WF+x1]*w11;
    out[id] = c;            // confidence = first output
    g_regup[id] = r;
}

// ---------------- refinement conv1: 4->32, relu, channel-last hidden ----------------
__global__ void __launch_bounds__(256) k_ref1(const float* __restrict__ img,
                                              const float* __restrict__ W,
                                              const float* __restrict__ Bi) {
    __shared__ float ws[1152];  // [(ci*9+tap)*32 + o]
    __shared__ float bs[32];
    for (int i = threadIdx.x; i < 1152; i += blockDim.x) {
        int o = i & 31; int rest = i >> 5; int tap = rest % 9; int ci = rest / 9;
        ws[i] = W[(o*4+ci)*9 + tap];
    }
    if (threadIdx.x < 32) bs[threadIdx.x] = Bi[threadIdx.x];
    __syncthreads();

    int id = blockIdx.x*blockDim.x + threadIdx.x;   // H0*W0 threads
    int ow = id % W0; int oh = id / W0;
    float acc[32];
    #pragma unroll
    for (int o = 0; o < 32; o++) acc[o] = bs[o];
    for (int ci = 0; ci < 4; ci++)
        #pragma unroll
        for (int kh = 0; kh < 3; kh++) {
            int ih = oh + kh - 1; if ((unsigned)ih >= H0) continue;
            #pragma unroll
            for (int kw = 0; kw < 3; kw++) {
                int iw = ow + kw - 1; if ((unsigned)iw >= W0) continue;
                float v = (ci < 3) ? img[(ci*H0 + ih)*W0 + iw] : g_regup[ih*W0 + iw];
                const float* wp = ws + (ci*9 + kh*3 + kw)*32;
                #pragma unroll
                for (int o = 0; o < 32; o++) acc[o] += wp[o]*v;
            }
        }
    #pragma unroll
    for (int o = 0; o < 32; o++)
        g_hid[id*32 + o] = fmaxf(acc[o], 0.f);
}

// ---------------- refinement conv2: 32->1 + residual add ----------------
__global__ void __launch_bounds__(256) k_ref2(const float* __restrict__ W,
                                              const float* __restrict__ Bi,
                                              float* __restrict__ out) {
    __shared__ float sw[288];   // [tap*32 + c]
    for (int i = threadIdx.x; i < 288; i += blockDim.x) {
        int c = i & 31; int tap = i >> 5;
        sw[i] = W[c*9 + tap];
    }
    __syncthreads();

    int id = blockIdx.x*blockDim.x + threadIdx.x;   // H0*W0 threads
    int ow = id % W0; int oh = id / W0;
    float acc = Bi[0];
    #pragma unroll
    for (int kh = 0; kh < 3; kh++) {
        int ih = oh + kh - 1; if ((unsigned)ih >= H0) continue;
        #pragma unroll
        for (int kw = 0; kw < 3; kw++) {
            int iw = ow + kw - 1; if ((unsigned)iw >= W0) continue;
            const float4* p = (const float4*)(g_hid + (ih*W0 + iw)*32);
            const float* tw = sw + (kh*3 + kw)*32;
            #pragma unroll
            for (int q = 0; q < 8; q++) {
                float4 A = p[q];
                acc += A.x*tw[q*4] + A.y*tw[q*4+1] + A.z*tw[q*4+2] + A.w*tw[q*4+3];
            }
        }
    }
    out[H0*W0 + id] = acc + g_regup[id];   // refined = regressed + residual
}

// ---------------- launch ----------------
extern "C" void kernel_launch(void* const* d_in, const int* in_sizes, int n_in,
                              void* d_out, int out_size) {
    const float* images = (const float*)d_in[0];
    const float* K      = (const float*)d_in[1];
    const float* poses  = (const float*)d_in[2];
    const float* enc_w1 = (const float*)d_in[3];
    const float* enc_b1 = (const float*)d_in[4];
    const float* enc_w2 = (const float*)d_in[5];
    const float* enc_b2 = (const float*)d_in[6];
    const float* enc_w3 = (const float*)d_in[7];
    const float* enc_b3 = (const float*)d_in[8];
    const float* reg_w1 = (const float*)d_in[9];
    const float* reg_b1 = (const float*)d_in[10];
    const float* reg_w2 = (const float*)d_in[11];
    const float* reg_b2 = (const float*)d_in[12];
    const float* ref_w1 = (const float*)d_in[13];
    const float* ref_b1 = (const float*)d_in[14];
    const float* ref_w2 = (const float*)d_in[15];
    const float* ref_b2 = (const float*)d_in[16];
    float* out = (float*)d_out;

    k_init<<<1, 1>>>(K, poses);
    k_enc1<<<(NV*H1*W1)/256, 256>>>(images, enc_w1, enc_b1);
    k_enc2<<<(NV*H2*W2)/256, 256>>>(enc_w2, enc_b2);
    k_enc3<<<(4*NV*HF*WF)/256, 256>>>(enc_w3, enc_b3);
    k_cost<<<HF*WF, 128>>>();
    k_reg1<<<(ND*HF*(WF/2))/128, 128>>>(reg_w1, reg_b1);
    k_reg2<<<(ND*HF*WF)/256, 256>>>(reg_w2, reg_b2);
    k_soft<<<(HF*WF)/256, 256>>>();
    k_up<<<(H0*W0)/256, 256>>>(out);
    k_ref1<<<(H0*W0)/256, 256>>>(images, ref_w1, ref_b1);
    k_ref2<<<(H0*W0)/256, 256>>>(ref_w2, ref_b2, out);
}